// round 1
// baseline (speedup 1.0000x reference)
#include <cuda_runtime.h>
#include <math.h>

#define Bb 2
#define LL 2048
#define DM 512
#define DI 1024
#define DS 16
#define DR 32
#define NB 4
#define BL (Bb*LL)          /* 4096 */
#define DXC (DR + 2*DS)     /* 64 */

// ---------------- scratch (static device globals; no allocation) -------------
__device__ float g_x  [BL * DM];        // current activations (residual stream)
__device__ float g_xz [BL * 2 * DI];    // [xi | z]
__device__ float g_xc [BL * DI];        // conv + silu output
__device__ float g_dbc[BL * DXC];       // [dt_raw(32) | B(16) | C(16)]
__device__ float g_dt [BL * DI];        // softplus(dt_raw @ W_dt + b_dt)
__device__ float g_y  [BL * DI];        // scan output (pre out-proj)

// ---------------- init copy --------------------------------------------------
__global__ void k_copy_in(const float* __restrict__ x) {
    int i = blockIdx.x * 256 + threadIdx.x;
    if (i < BL * DM) g_x[i] = x[i];
}

// ---------------- 128x128x16 fp32 GEMM (optionally + residual from g_x) ------
// aSel: 0 -> A = g_x, else A = g_y
// cSel: 0 -> C = g_x, 1 -> C = g_xz, else C = cExt (d_out)
__global__ void __launch_bounds__(256) k_sgemm128(
    int aSel, const float* __restrict__ W, int cSel, float* __restrict__ cExt,
    int addRes, int M, int N, int K)
{
    const float* __restrict__ A = (aSel == 0) ? g_x : g_y;
    float* __restrict__ C = (cSel == 0) ? g_x : (cSel == 1) ? g_xz : cExt;

    __shared__ float As[16][132];  // A^T tile, padded
    __shared__ float Bs[16][128];

    const int tid = threadIdx.x;
    const int tx = tid & 15;       // n-group
    const int ty = tid >> 4;       // m-group
    const int row0 = blockIdx.y * 128;
    const int col0 = blockIdx.x * 128;

    const int mA = tid >> 2;              // 0..63
    const int kA = (tid & 3) << 2;        // 0,4,8,12
    const int kB = tid >> 5;              // 0..7
    const int nB = (tid & 31) << 2;       // 0..124

    float acc[8][8];
    #pragma unroll
    for (int i = 0; i < 8; i++)
        #pragma unroll
        for (int j = 0; j < 8; j++) acc[i][j] = 0.f;

    for (int k0 = 0; k0 < K; k0 += 16) {
        float4 a0 = *(const float4*)(A + (size_t)(row0 + mA) * K + k0 + kA);
        float4 a1 = *(const float4*)(A + (size_t)(row0 + mA + 64) * K + k0 + kA);
        As[kA + 0][mA] = a0.x; As[kA + 1][mA] = a0.y;
        As[kA + 2][mA] = a0.z; As[kA + 3][mA] = a0.w;
        As[kA + 0][mA + 64] = a1.x; As[kA + 1][mA + 64] = a1.y;
        As[kA + 2][mA + 64] = a1.z; As[kA + 3][mA + 64] = a1.w;

        *(float4*)&Bs[kB][nB]     = *(const float4*)(W + (size_t)(k0 + kB) * N + col0 + nB);
        *(float4*)&Bs[kB + 8][nB] = *(const float4*)(W + (size_t)(k0 + kB + 8) * N + col0 + nB);
        __syncthreads();

        #pragma unroll
        for (int kk = 0; kk < 16; kk++) {
            float ar[8], br[8];
            *(float4*)(ar)     = *(const float4*)&As[kk][ty * 8];
            *(float4*)(ar + 4) = *(const float4*)&As[kk][ty * 8 + 4];
            *(float4*)(br)     = *(const float4*)&Bs[kk][tx * 8];
            *(float4*)(br + 4) = *(const float4*)&Bs[kk][tx * 8 + 4];
            #pragma unroll
            for (int i = 0; i < 8; i++)
                #pragma unroll
                for (int j = 0; j < 8; j++)
                    acc[i][j] += ar[i] * br[j];
        }
        __syncthreads();
    }

    #pragma unroll
    for (int i = 0; i < 8; i++) {
        const int r = row0 + ty * 8 + i;
        #pragma unroll
        for (int j = 0; j < 8; j += 4) {
            const int c = col0 + tx * 8 + j;
            float4 v = make_float4(acc[i][j], acc[i][j+1], acc[i][j+2], acc[i][j+3]);
            if (addRes) {
                float4 rv = *(const float4*)(g_x + (size_t)r * N + c);
                v.x += rv.x; v.y += rv.y; v.z += rv.z; v.w += rv.w;
            }
            *(float4*)(C + (size_t)r * N + c) = v;
        }
    }
}

// ---------------- GEMM2: g_dbc = g_xc @ W_x  (4096x64, K=1024) ---------------
__global__ void __launch_bounds__(256) k_dbc_gemm(const float* __restrict__ W)
{
    __shared__ float As[16][68];
    __shared__ float Bs[16][64];

    const int tid = threadIdx.x;
    const int tx = tid & 15, ty = tid >> 4;
    const int row0 = blockIdx.x * 64;
    const int mA = tid >> 2, kA = (tid & 3) << 2;
    const int kB = tid >> 4, nB = (tid & 15) << 2;

    float acc[4][4];
    #pragma unroll
    for (int i = 0; i < 4; i++)
        #pragma unroll
        for (int j = 0; j < 4; j++) acc[i][j] = 0.f;

    for (int k0 = 0; k0 < DI; k0 += 16) {
        float4 a = *(const float4*)(g_xc + (size_t)(row0 + mA) * DI + k0 + kA);
        As[kA + 0][mA] = a.x; As[kA + 1][mA] = a.y;
        As[kA + 2][mA] = a.z; As[kA + 3][mA] = a.w;
        *(float4*)&Bs[kB][nB] = *(const float4*)(W + (size_t)(k0 + kB) * DXC + nB);
        __syncthreads();

        #pragma unroll
        for (int kk = 0; kk < 16; kk++) {
            float ar[4], br[4];
            *(float4*)ar = *(const float4*)&As[kk][ty * 4];
            *(float4*)br = *(const float4*)&Bs[kk][tx * 4];
            #pragma unroll
            for (int i = 0; i < 4; i++)
                #pragma unroll
                for (int j = 0; j < 4; j++)
                    acc[i][j] += ar[i] * br[j];
        }
        __syncthreads();
    }

    #pragma unroll
    for (int i = 0; i < 4; i++) {
        const int r = row0 + ty * 4 + i;
        *(float4*)(g_dbc + (size_t)r * DXC + tx * 4) =
            make_float4(acc[i][0], acc[i][1], acc[i][2], acc[i][3]);
    }
}

// ---------------- causal depthwise conv(4) + bias + SiLU ---------------------
__global__ void k_conv_silu(const float* __restrict__ cw, const float* __restrict__ cb)
{
    const int idx = blockIdx.x * 256 + threadIdx.x;
    if (idx >= BL * DI) return;
    const int d  = idx & (DI - 1);
    const int ml = idx >> 10;           // b*L + l
    const int l  = ml & (LL - 1);

    float acc = cb[d];
    #pragma unroll
    for (int k = 0; k < 4; k++) {
        const int ls = l - 3 + k;
        if (ls >= 0)
            acc += cw[d * 4 + k] * g_xz[(size_t)(ml - 3 + k) * (2 * DI) + d];
    }
    const float sg = 1.f / (1.f + expf(-acc));
    g_xc[idx] = acc * sg;
}

// ---------------- dt = softplus(dt_raw @ W_dt + b_dt), K=32 ------------------
#define DT_MT 32
__global__ void __launch_bounds__(256) k_dt(const float* __restrict__ W_dt,
                                            const float* __restrict__ b_dt)
{
    const int d  = blockIdx.x * 256 + threadIdx.x;
    const int m0 = blockIdx.y * DT_MT;
    __shared__ float s[DT_MT][33];

    for (int e = threadIdx.x; e < DT_MT * 32; e += 256) {
        const int mm = e >> 5, r = e & 31;
        s[mm][r] = g_dbc[(size_t)(m0 + mm) * DXC + r];
    }
    __syncthreads();

    float w[32];
    #pragma unroll
    for (int r = 0; r < 32; r++) w[r] = W_dt[(size_t)r * DI + d];
    const float bias = b_dt[d];

    for (int mm = 0; mm < DT_MT; mm++) {
        float acc = bias;
        #pragma unroll
        for (int r = 0; r < 32; r++) acc += s[mm][r] * w[r];
        const float v = (acc > 20.f) ? acc : log1pf(expf(acc));
        g_dt[(size_t)(m0 + mm) * DI + d] = v;
    }
}

// ---------------- selective scan + gating epilogue ---------------------------
// block = 128 threads = 8 channels x 16 states; grid = B * DI/8 = 256 blocks
__global__ void __launch_bounds__(128) k_scan(const float* __restrict__ A_log,
                                              const float* __restrict__ Dp)
{
    const int t  = threadIdx.x;
    const int s  = t & 15;                  // state index
    const int dl = t >> 4;                  // local channel 0..7
    const int bb = blockIdx.x;
    const int b  = bb >> 7;                 // 128 channel-groups per batch
    const int d  = (bb & 127) * 8 + dl;

    const float A  = -expf(A_log[d * DS + s]);
    const float Dv = Dp[d];
    float h = 0.f;
    const int base = b * LL;

    #pragma unroll 2
    for (int l = 0; l < LL; l++) {
        const int m = base + l;
        const float dtv = g_dt[(size_t)m * DI + d];   // broadcast within 16-lane group
        const float xcv = g_xc[(size_t)m * DI + d];
        const float Bv  = g_dbc[(size_t)m * DXC + DR + s];
        const float Cv  = g_dbc[(size_t)m * DXC + DR + DS + s];

        h = h * expf(dtv * A) + (dtv * xcv) * Bv;

        float p = h * Cv;
        p += __shfl_xor_sync(0xffffffffu, p, 8);
        p += __shfl_xor_sync(0xffffffffu, p, 4);
        p += __shfl_xor_sync(0xffffffffu, p, 2);
        p += __shfl_xor_sync(0xffffffffu, p, 1);

        if (s == 0) {
            const float zv = g_xz[(size_t)m * (2 * DI) + DI + d];
            const float yv = (p + xcv * Dv) * (zv / (1.f + expf(-zv)));
            g_y[(size_t)m * DI + d] = yv;
        }
    }
}

// ---------------- launch ------------------------------------------------------
extern "C" void kernel_launch(void* const* d_in, const int* in_sizes, int n_in,
                              void* d_out, int out_size)
{
    const float* x     = (const float*)d_in[0];
    const float* W_in  = (const float*)d_in[1];
    const float* convw = (const float*)d_in[2];
    const float* convb = (const float*)d_in[3];
    const float* W_x   = (const float*)d_in[4];
    const float* W_dt  = (const float*)d_in[5];
    const float* b_dt  = (const float*)d_in[6];
    const float* A_log = (const float*)d_in[7];
    const float* Dp    = (const float*)d_in[8];
    const float* W_out = (const float*)d_in[9];
    float* out = (float*)d_out;

    k_copy_in<<<(BL * DM + 255) / 256, 256>>>(x);

    for (int i = 0; i < NB; i++) {
        // xz = x @ W_in   (4096 x 2048, K=512)
        k_sgemm128<<<dim3(2 * DI / 128, BL / 128), 256>>>(
            0, W_in + (size_t)i * DM * 2 * DI, 1, nullptr, 0, BL, 2 * DI, DM);

        // conv + silu
        k_conv_silu<<<(BL * DI) / 256, 256>>>(convw + (size_t)i * DI * 4,
                                              convb + (size_t)i * DI);

        // dbc = xc @ W_x  (4096 x 64, K=1024)
        k_dbc_gemm<<<BL / 64, 256>>>(W_x + (size_t)i * DI * DXC);

        // dt = softplus(dt_raw @ W_dt + b_dt)
        k_dt<<<dim3(DI / 256, BL / DT_MT), 256>>>(W_dt + (size_t)i * DR * DI,
                                                  b_dt + (size_t)i * DI);

        // selective scan + gating
        k_scan<<<Bb * (DI / 8), 128>>>(A_log + (size_t)i * DI * DS,
                                       Dp + (size_t)i * DI);

        // x = y @ W_out + x   (4096 x 512, K=1024); last block writes d_out
        k_sgemm128<<<dim3(DM / 128, BL / 128), 256>>>(
            1, W_out + (size_t)i * DI * DM, (i == NB - 1) ? 2 : 0, out, 1, BL, DM, DI);
    }
}

// round 2
// speedup vs baseline: 1.1313x; 1.1313x over previous
#include <cuda_runtime.h>
#include <math.h>
#include <cstdint>

#define Bb 2
#define LL 2048
#define DM 512
#define DI 1024
#define DS 16
#define DR 32
#define NB 4
#define BL (Bb*LL)          /* 4096 */
#define DXC (DR + 2*DS)     /* 64 */

// ---------------- scratch (static device globals; no allocation) -------------
__device__ float g_x  [BL * DM];        // residual stream
__device__ float g_xz [BL * 2 * DI];    // [xi | z]
__device__ float g_xc [BL * DI];        // conv + silu output
__device__ float g_dbc[BL * DXC];       // [dt_raw(32) | B(16) | C(16)]
__device__ float g_dt [BL * DI];
__device__ float g_y  [BL * DI];

// ---------------- tf32 tensor-core GEMM: C = A[M,K] @ W[K,N] (+R) ------------
#define ASTR 20     /* 16 + 4 pad floats */
#define BSTR 136    /* 128 + 8 pad floats */

__device__ __forceinline__ uint32_t f2tf32(float x) {
    uint32_t u; asm("cvt.rna.tf32.f32 %0, %1;" : "=r"(u) : "f"(x)); return u;
}

__global__ void __launch_bounds__(256, 2) k_mma(
    const float* __restrict__ A, const float* __restrict__ W,
    float* __restrict__ C, const float* __restrict__ R,
    int M, int N, int K, int addRes)
{
    __shared__ float As[2][128 * ASTR];
    __shared__ float Bs[2][16 * BSTR];

    const int tid  = threadIdx.x;
    const int lane = tid & 31, warp = tid >> 5;
    const int row0 = blockIdx.y * 128, col0 = blockIdx.x * 128;
    const int wm = (warp & 1) * 64, wn = (warp >> 1) * 32;
    const int ra = lane >> 2, ca = lane & 3;

    const uint32_t sA = (uint32_t)__cvta_generic_to_shared(&As[0][0]);
    const uint32_t sB = (uint32_t)__cvta_generic_to_shared(&Bs[0][0]);

    float acc[4][4][4];
    #pragma unroll
    for (int i = 0; i < 4; i++)
        #pragma unroll
        for (int j = 0; j < 4; j++)
            #pragma unroll
            for (int q = 0; q < 4; q++) acc[i][j][q] = 0.f;

    const int stages = K >> 4;

    auto load_stage = [&](int s, int buf) {
        const int k0 = s << 4;
        const uint32_t a_base = sA + (uint32_t)buf * (128 * ASTR * 4);
        const uint32_t b_base = sB + (uint32_t)buf * (16 * BSTR * 4);
        #pragma unroll
        for (int r = 0; r < 2; r++) {
            const int f = tid + r * 256;
            const int row = f >> 2, k4 = (f & 3) << 2;
            const float* src = A + (size_t)(row0 + row) * K + k0 + k4;
            asm volatile("cp.async.ca.shared.global [%0], [%1], 16;\n"
                :: "r"(a_base + (uint32_t)(row * ASTR + k4) * 4), "l"(src));
        }
        #pragma unroll
        for (int r = 0; r < 2; r++) {
            const int f = tid + r * 256;
            const int kk = f >> 5, n4 = (f & 31) << 2;
            const bool ok = (col0 + n4) < N;
            const float* src = ok ? (W + (size_t)(k0 + kk) * N + col0 + n4) : W;
            const int sz = ok ? 16 : 0;
            asm volatile("cp.async.ca.shared.global [%0], [%1], 16, %2;\n"
                :: "r"(b_base + (uint32_t)(kk * BSTR + n4) * 4), "l"(src), "r"(sz));
        }
        asm volatile("cp.async.commit_group;\n");
    };

    auto compute_stage = [&](int buf) {
        const float* a_s = &As[buf][0];
        const float* b_s = &Bs[buf][0];
        #pragma unroll
        for (int kk = 0; kk < 16; kk += 8) {
            uint32_t af[4][4], bf[4][2];
            #pragma unroll
            for (int i = 0; i < 4; i++) {
                const float* p = a_s + (wm + i * 16 + ra) * ASTR + kk + ca;
                af[i][0] = f2tf32(p[0]);
                af[i][1] = f2tf32(p[8 * ASTR]);
                af[i][2] = f2tf32(p[4]);
                af[i][3] = f2tf32(p[8 * ASTR + 4]);
            }
            #pragma unroll
            for (int j = 0; j < 4; j++) {
                const float* q = b_s + (kk + ca) * BSTR + wn + j * 8 + ra;
                bf[j][0] = f2tf32(q[0]);
                bf[j][1] = f2tf32(q[4 * BSTR]);
            }
            #pragma unroll
            for (int i = 0; i < 4; i++)
                #pragma unroll
                for (int j = 0; j < 4; j++)
                    asm volatile(
                        "mma.sync.aligned.m16n8k8.row.col.f32.tf32.tf32.f32 "
                        "{%0,%1,%2,%3}, {%4,%5,%6,%7}, {%8,%9}, {%0,%1,%2,%3};"
                        : "+f"(acc[i][j][0]), "+f"(acc[i][j][1]),
                          "+f"(acc[i][j][2]), "+f"(acc[i][j][3])
                        : "r"(af[i][0]), "r"(af[i][1]), "r"(af[i][2]), "r"(af[i][3]),
                          "r"(bf[j][0]), "r"(bf[j][1]));
        }
    };

    load_stage(0, 0);
    asm volatile("cp.async.wait_group 0;\n");
    __syncthreads();

    for (int s = 0; s < stages; s++) {
        if (s + 1 < stages) load_stage(s + 1, (s + 1) & 1);
        compute_stage(s & 1);
        asm volatile("cp.async.wait_group 0;\n");
        __syncthreads();
    }

    #pragma unroll
    for (int i = 0; i < 4; i++) {
        const int r = row0 + wm + i * 16 + ra;
        #pragma unroll
        for (int j = 0; j < 4; j++) {
            const int c = col0 + wn + j * 8 + ca * 2;
            if (c < N) {
                const size_t o0 = (size_t)r * N + c;
                const size_t o1 = (size_t)(r + 8) * N + c;
                float2 v0 = make_float2(acc[i][j][0], acc[i][j][1]);
                float2 v1 = make_float2(acc[i][j][2], acc[i][j][3]);
                if (addRes) {
                    float2 q0 = *(const float2*)(R + o0);
                    float2 q1 = *(const float2*)(R + o1);
                    v0.x += q0.x; v0.y += q0.y; v1.x += q1.x; v1.y += q1.y;
                }
                *(float2*)(C + o0) = v0;
                *(float2*)(C + o1) = v1;
            }
        }
    }
}

// ---------------- causal depthwise conv(4) + bias + SiLU ---------------------
__global__ void k_conv_silu(const float* __restrict__ cw, const float* __restrict__ cb)
{
    const int idx = blockIdx.x * 256 + threadIdx.x;
    if (idx >= BL * DI) return;
    const int d  = idx & (DI - 1);
    const int ml = idx >> 10;
    const int l  = ml & (LL - 1);

    float acc = cb[d];
    #pragma unroll
    for (int k = 0; k < 4; k++) {
        const int ls = l - 3 + k;
        if (ls >= 0)
            acc += cw[d * 4 + k] * g_xz[(size_t)(ml - 3 + k) * (2 * DI) + d];
    }
    const float sg = 1.f / (1.f + __expf(-acc));
    g_xc[idx] = acc * sg;
}

// ---------------- dt = softplus(dt_raw @ W_dt + b_dt), K=32 ------------------
#define DT_MT 32
__global__ void __launch_bounds__(256) k_dt(const float* __restrict__ W_dt,
                                            const float* __restrict__ b_dt)
{
    const int d  = blockIdx.x * 256 + threadIdx.x;
    const int m0 = blockIdx.y * DT_MT;
    __shared__ float s[DT_MT][33];

    for (int e = threadIdx.x; e < DT_MT * 32; e += 256) {
        const int mm = e >> 5, r = e & 31;
        s[mm][r] = g_dbc[(size_t)(m0 + mm) * DXC + r];
    }
    __syncthreads();

    float w[32];
    #pragma unroll
    for (int r = 0; r < 32; r++) w[r] = W_dt[(size_t)r * DI + d];
    const float bias = b_dt[d];

    for (int mm = 0; mm < DT_MT; mm++) {
        float acc = bias;
        #pragma unroll
        for (int r = 0; r < 32; r++) acc += s[mm][r] * w[r];
        const float v = (acc > 20.f) ? acc : log1pf(__expf(acc));
        g_dt[(size_t)(m0 + mm) * DI + d] = v;
    }
}

// ---------------- selective scan + gating epilogue ---------------------------
__global__ void __launch_bounds__(128) k_scan(const float* __restrict__ A_log,
                                              const float* __restrict__ Dp)
{
    const int t  = threadIdx.x;
    const int s  = t & 15;
    const int dl = t >> 4;
    const int bb = blockIdx.x;
    const int b  = bb >> 7;
    const int d  = (bb & 127) * 8 + dl;

    const float A  = -__expf(A_log[d * DS + s]);
    const float Dv = Dp[d];
    float h = 0.f;
    const int base = b * LL;

    #pragma unroll 4
    for (int l = 0; l < LL; l++) {
        const int m = base + l;
        const float dtv = g_dt[(size_t)m * DI + d];
        const float xcv = g_xc[(size_t)m * DI + d];
        const float Bv  = g_dbc[(size_t)m * DXC + DR + s];
        const float Cv  = g_dbc[(size_t)m * DXC + DR + DS + s];

        h = h * __expf(dtv * A) + (dtv * xcv) * Bv;

        float p = h * Cv;
        p += __shfl_xor_sync(0xffffffffu, p, 8);
        p += __shfl_xor_sync(0xffffffffu, p, 4);
        p += __shfl_xor_sync(0xffffffffu, p, 2);
        p += __shfl_xor_sync(0xffffffffu, p, 1);

        if (s == 0) {
            const float zv = g_xz[(size_t)m * (2 * DI) + DI + d];
            const float yv = (p + xcv * Dv) * (zv / (1.f + __expf(-zv)));
            g_y[(size_t)m * DI + d] = yv;
        }
    }
}

// ---------------- launch ------------------------------------------------------
extern "C" void kernel_launch(void* const* d_in, const int* in_sizes, int n_in,
                              void* d_out, int out_size)
{
    const float* x     = (const float*)d_in[0];
    const float* W_in  = (const float*)d_in[1];
    const float* convw = (const float*)d_in[2];
    const float* convb = (const float*)d_in[3];
    const float* W_x   = (const float*)d_in[4];
    const float* W_dt  = (const float*)d_in[5];
    const float* b_dt  = (const float*)d_in[6];
    const float* A_log = (const float*)d_in[7];
    const float* Dp    = (const float*)d_in[8];
    const float* W_out = (const float*)d_in[9];
    float* out = (float*)d_out;

    float *px, *pxz, *pxc, *py;
    cudaGetSymbolAddress((void**)&px,  g_x);
    cudaGetSymbolAddress((void**)&pxz, g_xz);
    cudaGetSymbolAddress((void**)&pxc, g_xc);
    cudaGetSymbolAddress((void**)&py,  g_y);
    float* pdbc;
    cudaGetSymbolAddress((void**)&pdbc, g_dbc);

    for (int i = 0; i < NB; i++) {
        const float* a_in = (i == 0) ? x : px;

        // xz = x @ W_in   (4096 x 2048, K=512)
        k_mma<<<dim3(2 * DI / 128, BL / 128), 256>>>(
            a_in, W_in + (size_t)i * DM * 2 * DI, pxz, nullptr,
            BL, 2 * DI, DM, 0);

        // conv + silu
        k_conv_silu<<<(BL * DI) / 256, 256>>>(convw + (size_t)i * DI * 4,
                                              convb + (size_t)i * DI);

        // dbc = xc @ W_x  (4096 x 64, K=1024)
        k_mma<<<dim3(1, BL / 128), 256>>>(
            pxc, W_x + (size_t)i * DI * DXC, pdbc, nullptr,
            BL, DXC, DI, 0);

        // dt = softplus(dt_raw @ W_dt + b_dt)
        k_dt<<<dim3(DI / 256, BL / DT_MT), 256>>>(W_dt + (size_t)i * DR * DI,
                                                  b_dt + (size_t)i * DI);

        // selective scan + gating
        k_scan<<<Bb * (DI / 8), 128>>>(A_log + (size_t)i * DI * DS,
                                       Dp + (size_t)i * DI);

        // x = y @ W_out + resid   (4096 x 512, K=1024); last block -> d_out
        k_mma<<<dim3(DM / 128, BL / 128), 256>>>(
            py, W_out + (size_t)i * DI * DM,
            (i == NB - 1) ? out : px, a_in,
            BL, DM, DI, 1);
    }
}